// round 4
// baseline (speedup 1.0000x reference)
#include <cuda_runtime.h>
#include <cstdint>

#define HH 96
#define WW 96
#define HW (HH*WW)
#define NB 8
#define NBLK (NB*2)              // 16 blocks: one per (sample, direction)
#define NTHR 1024
#define NWORDS (HH*3)            // 288 mask words per image

__device__ unsigned g_max[NB];   // per-sample hausdorff, float bits (>=0); zero-init, self-reset
__device__ int      g_done = 0;

__global__ void __launch_bounds__(NTHR)
hausdorff_kernel(const float* __restrict__ pred,
                 const float* __restrict__ targ,
                 float* __restrict__ out)
{
    __shared__ uint32_t s_A[HH * 4];         // stride-4 rows, words 0..2 used
    __shared__ uint32_t s_B[HH * 4];
    __shared__ float    s_red[NTHR / 32];

    const int blk = blockIdx.x;
    const int dir = blk & 1;
    const int n   = blk >> 1;

    const int tid  = threadIdx.x;
    const int lane = tid & 31;
    const int warp = tid >> 5;

    // ---- Mask build: thread t < 288 owns one 32-bit word = 32 contiguous floats
    // = 8 contiguous float4 (128B chunk per image, per-warp 4KB contiguous = coalesced).
    // inputs are uniform [0,1): round(x) > 0.5  <=>  x > 0.5f  (0.5 ties round-even to 0)
    if (tid < NWORDS) {
        const int row  = tid / 3;
        const int wcol = tid - row * 3;
        const int base = row * 24 + wcol * 8;              // float4 index of bit 0
        const float4* pA4 = (const float4*)(pred + n * HW) + base;
        const float4* pB4 = (const float4*)(targ + n * HW) + base;

        float4 a[8], b[8];
        #pragma unroll
        for (int j = 0; j < 8; ++j) a[j] = pA4[j];         // 16 independent LDG.128
        #pragma unroll
        for (int j = 0; j < 8; ++j) b[j] = pB4[j];

        uint32_t wa = 0u, wb = 0u;
        #pragma unroll
        for (int j = 0; j < 8; ++j) {
            wa |= ((a[j].x > 0.5f ? 1u : 0u) | (a[j].y > 0.5f ? 2u : 0u)
                 | (a[j].z > 0.5f ? 4u : 0u) | (a[j].w > 0.5f ? 8u : 0u)) << (4 * j);
            wb |= ((b[j].x > 0.5f ? 1u : 0u) | (b[j].y > 0.5f ? 2u : 0u)
                 | (b[j].z > 0.5f ? 4u : 0u) | (b[j].w > 0.5f ? 8u : 0u)) << (4 * j);
        }
        const int wi = row * 4 + wcol;
        s_A[wi] = wa;
        s_B[wi] = wb;
        if (wcol == 0) { s_A[wi + 3] = 0u; s_B[wi + 3] = 0u; }   // zero pad word 3
    }
    __syncthreads();

    // dir 0: src = A & ~B, tgt = B;  dir 1: src = B & ~A, tgt = A
    const uint32_t* s_srcp = dir ? s_B : s_A;
    const uint32_t* s_tgt  = dir ? s_A : s_B;

    float lmax = -1.0f;

    #pragma unroll
    for (int k = 0; k < HW / NTHR; ++k) {                  // 9216 = 9 * 1024 exactly
        const int p = tid + k * NTHR;
        const int r = p / WW;
        const int c = p - r * WW;
        const int k0 = c >> 5;
        const uint32_t sw = s_srcp[r * 4 + k0] & ~s_tgt[r * 4 + k0];
        if (!((sw >> (c & 31)) & 1u)) continue;

        int best = 0x7FFFFFFF;                             // squared integer distance
        const int s = c & 31;
        const uint32_t maskR = 0xFFFFFFFFu << s;           // bits >= c within word k0
        const uint32_t maskL = (2u << s) - 1u;             // bits <= c within word k0

        // Expanding ring over rows; exact: row at |dy|=d contributes >= d^2.
        for (int d = 0; d < HH; ++d) {
            const int dd = d * d;
            if (dd >= best) break;
            #pragma unroll
            for (int side = 0; side < 2; ++side) {
                if (side && d == 0) continue;
                const int y = side ? (r + d) : (r - d);
                if ((unsigned)y >= (unsigned)HH) continue;
                const uint32_t* w = &s_tgt[y * 4];

                int dx = 10000;
                uint32_t m = w[k0] & maskR;                              // right side
                if (m) dx = (k0 << 5) + (__ffs(m) - 1) - c;
                else if (k0 < 2 && w[k0 + 1]) dx = ((k0 + 1) << 5) + (__ffs(w[k0 + 1]) - 1) - c;
                else if (k0 < 1 && w[2])      dx = 64 + (__ffs(w[2]) - 1) - c;

                int dl = 10000;                                          // left side
                m = w[k0] & maskL;
                if (m) dl = c - ((k0 << 5) + 31 - __clz(m));
                else if (k0 > 0 && w[k0 - 1]) dl = c - (((k0 - 1) << 5) + 31 - __clz(w[k0 - 1]));
                else if (k0 > 1 && w[0])      dl = c - (31 - __clz(w[0]));

                dx = min(dx, dl);
                if (dx < WW) best = min(best, dd + dx * dx);
            }
        }
        const float pd = (best == 0x7FFFFFFF) ? 1e9f
                                              : sqrtf((float)best) * (1.0f / 96.0f);
        lmax = fmaxf(lmax, pd);
    }

    // block max reduction (32 warps)
    for (int off = 16; off; off >>= 1)
        lmax = fmaxf(lmax, __shfl_xor_sync(0xFFFFFFFFu, lmax, off));
    if (lane == 0) s_red[warp] = lmax;
    __syncthreads();

    if (tid == 0) {
        float bm = s_red[0];
        #pragma unroll
        for (int i = 1; i < NTHR / 32; ++i) bm = fmaxf(bm, s_red[i]);
        bm = fmaxf(bm, 0.0f);                 // empty src set -> 0 (matches reference)
        atomicMax(&g_max[n], __float_as_uint(bm));   // valid: all values >= 0
        __threadfence();
        const int prev = atomicAdd(&g_done, 1);
        if (prev == NBLK - 1) {
            __threadfence();
            volatile unsigned* gm = g_max;
            float sum = 0.0f;
            #pragma unroll
            for (int i = 0; i < NB; ++i) sum += __uint_as_float(gm[i]);
            out[0] = sum * (1.0f / NB);
            #pragma unroll
            for (int i = 0; i < NB; ++i) gm[i] = 0u;  // reset for next graph replay
            g_done = 0;
        }
    }
}

extern "C" void kernel_launch(void* const* d_in, const int* in_sizes, int n_in,
                              void* d_out, int out_size)
{
    (void)in_sizes; (void)n_in; (void)out_size;
    const float* pred = (const float*)d_in[0];
    const float* targ = (const float*)d_in[1];
    hausdorff_kernel<<<NBLK, NTHR>>>(pred, targ, (float*)d_out);
}

// round 7
// speedup vs baseline: 1.2299x; 1.2299x over previous
#include <cuda_runtime.h>
#include <cstdint>

#define HH 96
#define WW 96
#define HW (HH*WW)
#define NB 8
#define SLICES 8
#define NBLK (NB*2*SLICES)       // 128 blocks: (sample, dir, slice)
#define NTHR 288                 // one thread per mask word; 9 warps
#define PTS_PER_BLK (HW/SLICES)  // 1152 = 288 * 4
#define NWORDS (HH*3)            // 288 mask words per image

__device__ unsigned g_max[NB];        // per-sample result, float bits (>=0); self-reset
__device__ int      g_done_s[NB];     // per-sample arrival counters (to 16); self-reset
__device__ int      g_done = 0;       // sample-group counter (to 8); self-reset

__global__ void __launch_bounds__(NTHR)
hausdorff_kernel(const float* __restrict__ pred,
                 const float* __restrict__ targ,
                 float* __restrict__ out)
{
    __shared__ uint32_t s_A[HH * 4];  // stride-4 rows, words 0..2 used, word 3 = 0
    __shared__ uint32_t s_B[HH * 4];
    __shared__ float    s_red[(NTHR + 31) / 32];

    const int blk   = blockIdx.x;
    const int slice = blk & (SLICES - 1);
    const int nd    = blk >> 3;           // n*2 + dir
    const int dir   = nd & 1;
    const int n     = nd >> 1;

    const int tid  = threadIdx.x;
    const int lane = tid & 31;
    const int warp = tid >> 5;

    // ---- Single-phase mask build: thread t owns mask word t (32 contiguous floats
    // = 8 contiguous float4 = 128B per image; per-warp 4KB contiguous -> coalesced).
    // inputs uniform [0,1): round(x) > 0.5  <=>  x > 0.5f  (0.5 ties round-even -> 0)
    {
        const int row  = tid / 3;
        const int wcol = tid - row * 3;
        const int base = row * 24 + wcol * 8;              // float4 index of bit 0
        const float4* pA4 = (const float4*)(pred + n * HW) + base;
        const float4* pB4 = (const float4*)(targ + n * HW) + base;

        float4 a[8], b[8];
        #pragma unroll
        for (int j = 0; j < 8; ++j) a[j] = pA4[j];         // 16 independent LDG.128
        #pragma unroll
        for (int j = 0; j < 8; ++j) b[j] = pB4[j];

        uint32_t wa = 0u, wb = 0u;
        #pragma unroll
        for (int j = 0; j < 8; ++j) {
            wa |= ((a[j].x > 0.5f ? 1u : 0u) | (a[j].y > 0.5f ? 2u : 0u)
                 | (a[j].z > 0.5f ? 4u : 0u) | (a[j].w > 0.5f ? 8u : 0u)) << (4 * j);
            wb |= ((b[j].x > 0.5f ? 1u : 0u) | (b[j].y > 0.5f ? 2u : 0u)
                 | (b[j].z > 0.5f ? 4u : 0u) | (b[j].w > 0.5f ? 8u : 0u)) << (4 * j);
        }
        const int wi = row * 4 + wcol;
        s_A[wi] = wa;
        s_B[wi] = wb;
        if (wcol == 0) { s_A[wi + 3] = 0u; s_B[wi + 3] = 0u; }   // zero pad word 3
    }
    __syncthreads();

    // dir 0: src = A & ~B, tgt = B;  dir 1: src = B & ~A, tgt = A
    const uint32_t* s_srcp = dir ? s_B : s_A;
    const uint32_t* s_tgt  = dir ? s_A : s_B;

    float lmax = -1.0f;   // holds max SQUARED distance (or sentinels)

    #pragma unroll
    for (int k = 0; k < 4; ++k) {                          // 1152 = 288 * 4
        const int p = slice * PTS_PER_BLK + tid + k * NTHR;
        const int r = p / WW;
        const int c = p - r * WW;
        const int k0 = c >> 5;
        const uint32_t sw = s_srcp[r * 4 + k0] & ~s_tgt[r * 4 + k0];
        if (!((sw >> (c & 31)) & 1u)) continue;

        int best = 0x7FFFFFFF;                             // squared integer distance
        const int s = c & 31;
        const uint32_t maskR = 0xFFFFFFFFu << s;           // bits >= c within word k0
        const uint32_t maskL = (2u << s) - 1u;             // bits <= c within word k0

        // Expanding ring over rows; exact: row at |dy|=d contributes >= d^2.
        for (int d = 0; d < HH; ++d) {
            const int dd = d * d;
            if (dd >= best) break;
            #pragma unroll
            for (int side = 0; side < 2; ++side) {
                if (side && d == 0) continue;
                const int y = side ? (r + d) : (r - d);
                if ((unsigned)y >= (unsigned)HH) continue;
                const uint32_t* w = &s_tgt[y * 4];

                int dx = 10000;
                uint32_t m = w[k0] & maskR;                              // right side
                if (m) dx = (k0 << 5) + (__ffs(m) - 1) - c;
                else if (k0 < 2 && w[k0 + 1]) dx = ((k0 + 1) << 5) + (__ffs(w[k0 + 1]) - 1) - c;
                else if (k0 < 1 && w[2])      dx = 64 + (__ffs(w[2]) - 1) - c;

                int dl = 10000;                                          // left side
                m = w[k0] & maskL;
                if (m) dl = c - ((k0 << 5) + 31 - __clz(m));
                else if (k0 > 0 && w[k0 - 1]) dl = c - (((k0 - 1) << 5) + 31 - __clz(w[k0 - 1]));
                else if (k0 > 1 && w[0])      dl = c - (31 - __clz(w[0]));

                dx = min(dx, dl);
                if (dx < WW) best = min(best, dd + dx * dx);
            }
        }
        // squared-distance domain; 3e9 sentinel = "target set empty" (> any real sq)
        const float fsq = (best == 0x7FFFFFFF) ? 3e9f : (float)best;
        lmax = fmaxf(lmax, fsq);
    }

    // block max reduction (9 warps) -- still in squared domain
    for (int off = 16; off; off >>= 1)
        lmax = fmaxf(lmax, __shfl_xor_sync(0xFFFFFFFFu, lmax, off));
    if (lane == 0) s_red[warp] = lmax;
    __syncthreads();

    if (tid == 0) {
        float bm = s_red[0];
        #pragma unroll
        for (int i = 1; i < (NTHR + 31) / 32; ++i) bm = fmaxf(bm, s_red[i]);
        // convert: empty src -> 0; empty tgt -> 1e9 (matches reference); else sqrt/96
        float v;
        if (bm < 0.0f)        v = 0.0f;
        else if (bm > 2e9f)   v = 1e9f;
        else                  v = sqrtf(bm) * (1.0f / 96.0f);
        atomicMax(&g_max[n], __float_as_uint(v));   // valid: all values >= 0
        __threadfence();
        // hierarchical completion: 16 blocks per sample, then 8 samples
        const int ps = atomicAdd(&g_done_s[n], 1);
        if (ps == 2 * SLICES - 1) {
            g_done_s[n] = 0;                        // reset own sample counter
            __threadfence();
            const int pg = atomicAdd(&g_done, 1);
            if (pg == NB - 1) {
                __threadfence();
                volatile unsigned* gm = g_max;
                float sum = 0.0f;
                #pragma unroll
                for (int i = 0; i < NB; ++i) sum += __uint_as_float(gm[i]);
                out[0] = sum * (1.0f / NB);
                #pragma unroll
                for (int i = 0; i < NB; ++i) gm[i] = 0u;  // reset for next replay
                g_done = 0;
            }
        }
    }
}

extern "C" void kernel_launch(void* const* d_in, const int* in_sizes, int n_in,
                              void* d_out, int out_size)
{
    (void)in_sizes; (void)n_in; (void)out_size;
    const float* pred = (const float*)d_in[0];
    const float* targ = (const float*)d_in[1];
    hausdorff_kernel<<<NBLK, NTHR>>>(pred, targ, (float*)d_out);
}